// round 9
// baseline (speedup 1.0000x reference)
#include <cuda_runtime.h>
#include <cuda_bf16.h>
#include <cstdint>

#define NNODES 50000
#define NEDGES 1600000
#define MAXF   512

// ---------------- device scratch (static, no allocation) ----------------
__device__ int   g_flag;
__device__ int   g_deg[NNODES];
__device__ float g_dinv[NNODES];
__device__ float g_diag[NNODES];
__device__ int   g_rowptr[NNODES + 1];
__device__ int   g_cursor[NNODES];
__device__ int   g_ecol[NEDGES];
__device__ float g_ew[NEDGES];
__device__ float g_T1 [(size_t)NNODES * MAXF];
__device__ float g_T1r[(size_t)NNODES * MAXF];
__device__ float g_T2r[(size_t)NNODES * MAXF];
__device__ float g_h1 [(size_t)NNODES * 250];
__device__ float g_h1r[(size_t)NNODES * 250];
__device__ float g_h2 [(size_t)NNODES * 500];
__device__ float g_h2r[(size_t)NNODES * 500];
__device__ float g_xr [(size_t)NNODES * 512];
__device__ float g_W1r[3 * 512 * 250];
__device__ float g_W2r[3 * 250 * 500];
__device__ float g_W3r[3 * 500 * 1000];

__device__ __forceinline__ float to_tf32(float x) {
    float y;
    asm("cvt.rna.tf32.f32 %0, %1;" : "=f"(y) : "f"(x));
    return y;
}

// ---------------- index width detection ----------------
__global__ void k_detect(const int* e32) {
    if (blockIdx.x == 0 && threadIdx.x == 0) {
        int is64 = 1;
        for (int i = 0; i < 512; ++i)
            if (e32[2 * i + 1] != 0) { is64 = 0; break; }
        g_flag = is64;
    }
}

__device__ __forceinline__ int load_idx(const void* e, long long i) {
    if (g_flag) return (int)((const long long*)e)[i];
    return ((const int*)e)[i];
}

// ---------------- graph setup ----------------
__global__ void k_init() {
    int i = blockIdx.x * blockDim.x + threadIdx.x;
    if (i < NNODES) { g_deg[i] = 0; g_cursor[i] = 0; }
}

__global__ void k_degree(const void* e) {
    int i = blockIdx.x * blockDim.x + threadIdx.x;
    if (i < NEDGES) {
        int dst = load_idx(e, (long long)NEDGES + i);
        atomicAdd(&g_deg[dst], 1);
    }
}

__global__ void k_node() {
    int i = blockIdx.x * blockDim.x + threadIdx.x;
    if (i < NNODES) {
        int d = g_deg[i];
        g_dinv[i] = d > 0 ? rsqrtf((float)d) : 0.0f;
        g_diag[i] = d > 0 ? 0.0f : -1.0f;
    }
}

__global__ void k_scan() {
    __shared__ int warp_sums[32];
    int tid  = threadIdx.x;
    int lane = tid & 31;
    int wid  = tid >> 5;
    int carry = 0;
    for (int base = 0; base < NNODES; base += 1024) {
        int i = base + tid;
        int v = (i < NNODES) ? g_deg[i] : 0;
        int x = v;
        #pragma unroll
        for (int o = 1; o < 32; o <<= 1) {
            int y = __shfl_up_sync(0xffffffffu, x, o);
            if (lane >= o) x += y;
        }
        if (lane == 31) warp_sums[wid] = x;
        __syncthreads();
        if (tid < 32) {
            int s = warp_sums[tid];
            #pragma unroll
            for (int o = 1; o < 32; o <<= 1) {
                int y = __shfl_up_sync(0xffffffffu, s, o);
                if (tid >= o) s += y;
            }
            warp_sums[tid] = s;
        }
        __syncthreads();
        int incl = x + (wid > 0 ? warp_sums[wid - 1] : 0);
        if (i < NNODES) g_rowptr[i] = carry + incl - v;
        int total = warp_sums[31];
        __syncthreads();
        carry += total;
    }
    if (tid == 0) g_rowptr[NNODES] = carry;
}

__global__ void k_scatter(const void* e) {
    int i = blockIdx.x * blockDim.x + threadIdx.x;
    if (i < NEDGES) {
        int src = load_idx(e, i);
        int dst = load_idx(e, (long long)NEDGES + i);
        float w = -g_dinv[dst] * g_dinv[src];
        int pos = g_rowptr[dst] + atomicAdd(&g_cursor[dst], 1);
        g_ecol[pos] = src;
        g_ew[pos]   = w;
    }
}

// ---------------- rounding helper kernel (tf32-round a buffer) ----------------
__global__ void k_round(const float* __restrict__ in, float* __restrict__ dst, int n) {
    int i = blockIdx.x * blockDim.x + threadIdx.x;
    if (i < n) dst[i] = to_tf32(in[i]);
}

// ---------------- vectorized SpMM with dual (plain + tf32-rounded) outputs ----
__global__ void k_spmm_v4(const float4* __restrict__ h, const float4* __restrict__ t0,
                          float4* __restrict__ out, float4* __restrict__ out_r,
                          int F4, int mode) {
    int node = blockIdx.x;
    int f = threadIdx.x;
    if (f >= F4) return;
    int s = g_rowptr[node];
    int e = g_rowptr[node + 1];
    float4 acc = make_float4(0.f, 0.f, 0.f, 0.f);
    for (int j = s; j < e; ++j) {
        int   src = __ldg(&g_ecol[j]);
        float w   = __ldg(&g_ew[j]);
        float4 v = __ldg(&h[(size_t)src * F4 + f]);
        acc.x = fmaf(w, v.x, acc.x);
        acc.y = fmaf(w, v.y, acc.y);
        acc.z = fmaf(w, v.z, acc.z);
        acc.w = fmaf(w, v.w, acc.w);
    }
    float dw = g_diag[node];
    float4 hv = __ldg(&h[(size_t)node * F4 + f]);
    acc.x = fmaf(dw, hv.x, acc.x);
    acc.y = fmaf(dw, hv.y, acc.y);
    acc.z = fmaf(dw, hv.z, acc.z);
    acc.w = fmaf(dw, hv.w, acc.w);
    if (mode) {
        float4 t = __ldg(&t0[(size_t)node * F4 + f]);
        acc.x = 2.f * acc.x - t.x;
        acc.y = 2.f * acc.y - t.y;
        acc.z = 2.f * acc.z - t.z;
        acc.w = 2.f * acc.w - t.w;
    }
    size_t idx = (size_t)node * F4 + f;
    if (out) out[idx] = acc;
    if (out_r) {
        float4 r = make_float4(to_tf32(acc.x), to_tf32(acc.y), to_tf32(acc.z), to_tf32(acc.w));
        out_r[idx] = r;
    }
}

__global__ void k_spmm_v2(const float2* __restrict__ h, const float2* __restrict__ t0,
                          float2* __restrict__ out, float2* __restrict__ out_r,
                          int F2, int mode) {
    int node = blockIdx.x;
    int f = threadIdx.x;
    if (f >= F2) return;
    int s = g_rowptr[node];
    int e = g_rowptr[node + 1];
    float2 acc = make_float2(0.f, 0.f);
    for (int j = s; j < e; ++j) {
        int   src = __ldg(&g_ecol[j]);
        float w   = __ldg(&g_ew[j]);
        float2 v = __ldg(&h[(size_t)src * F2 + f]);
        acc.x = fmaf(w, v.x, acc.x);
        acc.y = fmaf(w, v.y, acc.y);
    }
    float dw = g_diag[node];
    float2 hv = __ldg(&h[(size_t)node * F2 + f]);
    acc.x = fmaf(dw, hv.x, acc.x);
    acc.y = fmaf(dw, hv.y, acc.y);
    if (mode) {
        float2 t = __ldg(&t0[(size_t)node * F2 + f]);
        acc.x = 2.f * acc.x - t.x;
        acc.y = 2.f * acc.y - t.y;
    }
    size_t idx = (size_t)node * F2 + f;
    if (out) out[idx] = acc;
    if (out_r) out_r[idx] = make_float2(to_tf32(acc.x), to_tf32(acc.y));
}

// ---------------- TF32 tensor-core fused GEMM, cp.async 3-stage, 64x64 warp tile
__device__ __forceinline__ void mma_tf32(float* c, const uint32_t* a, const uint32_t* b) {
    asm volatile(
        "mma.sync.aligned.m16n8k8.row.col.f32.tf32.tf32.f32 "
        "{%0,%1,%2,%3}, {%4,%5,%6,%7}, {%8,%9}, {%0,%1,%2,%3};"
        : "+f"(c[0]), "+f"(c[1]), "+f"(c[2]), "+f"(c[3])
        : "r"(a[0]), "r"(a[1]), "r"(a[2]), "r"(a[3]), "r"(b[0]), "r"(b[1]));
}

__device__ __forceinline__ void cp_async8(uint32_t dst, const void* src, int sz) {
    asm volatile("cp.async.ca.shared.global [%0], [%1], 8, %2;"
                 :: "r"(dst), "l"(src), "r"(sz));
}
__device__ __forceinline__ void cp_commit() { asm volatile("cp.async.commit_group;"); }
template<int N> __device__ __forceinline__ void cp_wait() {
    asm volatile("cp.async.wait_group %0;" :: "n"(N));
}

#define GBM 128
#define GBN 256
#define GBK 16
#define GST 3          // pipeline stages
#define ASTRIDE 20     // A smem row stride (floats), conflict-free
#define BSTRIDE 264    // B smem row stride (floats), conflict-free (264 % 32 == 8)
#define GSMEM ((GST*GBM*ASTRIDE + GST*GBK*BSTRIDE) * 4)

__global__ __launch_bounds__(256, 1) void k_gemm3_tc(
    const float* __restrict__ A0, const float* __restrict__ A1,
    const float* __restrict__ A2, const float* __restrict__ W,
    const float* __restrict__ bias, float* __restrict__ out,
    float* __restrict__ out_r, int M, int K, int Nout)
{
    extern __shared__ float smem[];
    float* As = smem;                         // [GST][128][ASTRIDE]
    float* Bs = smem + GST * GBM * ASTRIDE;   // [GST][16][BSTRIDE]
    uint32_t sA = (uint32_t)__cvta_generic_to_shared(As);
    uint32_t sB = (uint32_t)__cvta_generic_to_shared(Bs);

    int tid  = threadIdx.x;
    int wid  = tid >> 5;
    int lane = tid & 31;
    int g    = lane >> 2;
    int tig  = lane & 3;
    int wm   = wid & 1;      // warp m (0..1): 64 rows
    int wn   = wid >> 1;     // warp n (0..3): 64 cols
    int bm   = blockIdx.y * GBM;
    int bn   = blockIdx.x * GBN;

    int kt = (K + GBK - 1) / GBK;
    int nt = 3 * kt;

    float acc[4][8][4];
    #pragma unroll
    for (int mi = 0; mi < 4; ++mi)
        #pragma unroll
        for (int ni = 0; ni < 8; ++ni)
            #pragma unroll
            for (int r = 0; r < 4; ++r) acc[mi][ni][r] = 0.0f;

    // A tile 128x16 = 1024 pairs (4 iters); B tile 16x256 = 2048 pairs (8 iters)
    auto issue_tile = [&](int t) {
        int pn = t / kt;
        int k0 = (t - pn * kt) * GBK;
        int s  = t % GST;
        const float* A = (pn == 0) ? A0 : ((pn == 1) ? A1 : A2);
        #pragma unroll
        for (int q = 0; q < 4; ++q) {
            int p  = q * 256 + tid;
            int m  = p >> 3;
            int kk = (p & 7) * 2;
            int gm = bm + m, gk = k0 + kk;
            int sz = (gm < M && gk < K) ? 8 : 0;
            const float* src = sz ? (A + (size_t)gm * K + gk) : A;
            uint32_t dst = sA + (uint32_t)(((s * GBM + m) * ASTRIDE + kk) * 4);
            cp_async8(dst, src, sz);
        }
        const float* B = W + (size_t)pn * K * Nout;
        #pragma unroll
        for (int q = 0; q < 8; ++q) {
            int p  = q * 256 + tid;
            int r  = p >> 7;
            int n0 = (p & 127) * 2;
            int gk = k0 + r, gn = bn + n0;
            int sz = (gk < K && gn + 1 < Nout) ? 8 : 0;   // Nout even -> pair in/out
            const float* src = sz ? (B + (size_t)gk * Nout + gn) : B;
            uint32_t dst = sB + (uint32_t)(((s * GBK + r) * BSTRIDE + n0) * 4);
            cp_async8(dst, src, sz);
        }
    };

    #pragma unroll
    for (int t = 0; t < GST - 1; ++t) {
        issue_tile(t);
        cp_commit();
    }

    for (int t = 0; t < nt; ++t) {
        cp_wait<GST - 2>();
        __syncthreads();

        int tn = t + GST - 1;
        if (tn < nt) issue_tile(tn);
        cp_commit();

        int s = t % GST;
        const float* Ab = As + s * GBM * ASTRIDE;
        const float* Bb = Bs + s * GBK * BSTRIDE;
        #pragma unroll
        for (int ks = 0; ks < GBK; ks += 8) {
            uint32_t af[4][4];
            uint32_t bf[8][2];
            #pragma unroll
            for (int mi = 0; mi < 4; ++mi) {
                int mb = wm * 64 + mi * 16;
                af[mi][0] = __float_as_uint(Ab[(mb + g    ) * ASTRIDE + ks + tig    ]);
                af[mi][1] = __float_as_uint(Ab[(mb + g + 8) * ASTRIDE + ks + tig    ]);
                af[mi][2] = __float_as_uint(Ab[(mb + g    ) * ASTRIDE + ks + tig + 4]);
                af[mi][3] = __float_as_uint(Ab[(mb + g + 8) * ASTRIDE + ks + tig + 4]);
            }
            #pragma unroll
            for (int ni = 0; ni < 8; ++ni) {
                int nb = wn * 64 + ni * 8;
                bf[ni][0] = __float_as_uint(Bb[(ks + tig    ) * BSTRIDE + nb + g]);
                bf[ni][1] = __float_as_uint(Bb[(ks + tig + 4) * BSTRIDE + nb + g]);
            }
            #pragma unroll
            for (int mi = 0; mi < 4; ++mi)
                #pragma unroll
                for (int ni = 0; ni < 8; ++ni)
                    mma_tf32(acc[mi][ni], af[mi], bf[ni]);
        }
        __syncthreads();
    }

    // ---- epilogue: bias + relu; plain + rounded outputs ----
    #pragma unroll
    for (int mi = 0; mi < 4; ++mi) {
        int r0 = bm + wm * 64 + mi * 16 + g;
        int r1 = r0 + 8;
        #pragma unroll
        for (int ni = 0; ni < 8; ++ni) {
            int c0 = bn + wn * 64 + ni * 8 + 2 * tig;
            float bv0 = (c0     < Nout) ? bias[c0]     : 0.0f;
            float bv1 = (c0 + 1 < Nout) ? bias[c0 + 1] : 0.0f;
            float v;
            if (r0 < M) {
                if (c0 < Nout) {
                    v = acc[mi][ni][0] + bv0; v = v > 0.f ? v : 0.f;
                    out[(size_t)r0 * Nout + c0] = v;
                    if (out_r) out_r[(size_t)r0 * Nout + c0] = to_tf32(v);
                }
                if (c0 + 1 < Nout) {
                    v = acc[mi][ni][1] + bv1; v = v > 0.f ? v : 0.f;
                    out[(size_t)r0 * Nout + c0 + 1] = v;
                    if (out_r) out_r[(size_t)r0 * Nout + c0 + 1] = to_tf32(v);
                }
            }
            if (r1 < M) {
                if (c0 < Nout) {
                    v = acc[mi][ni][2] + bv0; v = v > 0.f ? v : 0.f;
                    out[(size_t)r1 * Nout + c0] = v;
                    if (out_r) out_r[(size_t)r1 * Nout + c0] = to_tf32(v);
                }
                if (c0 + 1 < Nout) {
                    v = acc[mi][ni][3] + bv1; v = v > 0.f ? v : 0.f;
                    out[(size_t)r1 * Nout + c0 + 1] = v;
                    if (out_r) out_r[(size_t)r1 * Nout + c0 + 1] = to_tf32(v);
                }
            }
        }
    }
}

// ---------------- host side ----------------
static inline int ceil_div(int a, int b) { return (a + b - 1) / b; }

static void run_spmm(const float* h, const float* t0, float* out, float* out_r,
                     int F, int mode) {
    if (F % 4 == 0 || F == 500) {
        int F4 = F / 4;
        k_spmm_v4<<<NNODES, F4>>>((const float4*)h, (const float4*)t0,
                                  (float4*)out, (float4*)out_r, F4, mode);
    } else {
        int F2 = F / 2;
        k_spmm_v2<<<NNODES, F2>>>((const float2*)h, (const float2*)t0,
                                  (float2*)out, (float2*)out_r, F2, mode);
    }
}

static void run_layer(const float* h, const float* hr, int Fin, int Fout,
                      const float* Wr, const float* bias,
                      float* hout, float* hout_r,
                      float* T1, float* T1r, float* T2r) {
    run_spmm(h, nullptr, T1, T1r, Fin, 0);
    run_spmm(T1, h, nullptr, T2r, Fin, 1);
    dim3 ggrid(ceil_div(Fout, GBN), ceil_div(NNODES, GBM));
    k_gemm3_tc<<<ggrid, 256, GSMEM>>>(hr, T1r, T2r, Wr, bias, hout, hout_r,
                                      NNODES, Fin, Fout);
}

extern "C" void kernel_launch(void* const* d_in, const int* in_sizes, int n_in,
                              void* d_out, int out_size) {
    const float* x  = (const float*)d_in[0];
    const void*  ei = d_in[1];
    const float* w1 = (const float*)d_in[2];
    const float* b1 = (const float*)d_in[3];
    const float* w2 = (const float*)d_in[4];
    const float* b2 = (const float*)d_in[5];
    const float* w3 = (const float*)d_in[6];
    const float* b3 = (const float*)d_in[7];
    float* out = (float*)d_out;

    static bool attr_set = false;
    if (!attr_set) {
        cudaFuncSetAttribute(k_gemm3_tc, cudaFuncAttributeMaxDynamicSharedMemorySize, GSMEM);
        attr_set = true;
    }

    float *T1, *T1r, *T2r, *h1, *h1r, *h2, *h2r, *xr, *W1r, *W2r, *W3r;
    cudaGetSymbolAddress((void**)&T1,  g_T1);
    cudaGetSymbolAddress((void**)&T1r, g_T1r);
    cudaGetSymbolAddress((void**)&T2r, g_T2r);
    cudaGetSymbolAddress((void**)&h1,  g_h1);
    cudaGetSymbolAddress((void**)&h1r, g_h1r);
    cudaGetSymbolAddress((void**)&h2,  g_h2);
    cudaGetSymbolAddress((void**)&h2r, g_h2r);
    cudaGetSymbolAddress((void**)&xr,  g_xr);
    cudaGetSymbolAddress((void**)&W1r, g_W1r);
    cudaGetSymbolAddress((void**)&W2r, g_W2r);
    cudaGetSymbolAddress((void**)&W3r, g_W3r);

    // graph setup (recomputed every call: deterministic, graph-capturable)
    k_detect<<<1, 1>>>((const int*)ei);
    k_init<<<ceil_div(NNODES, 256), 256>>>();
    k_degree<<<ceil_div(NEDGES, 256), 256>>>(ei);
    k_node<<<ceil_div(NNODES, 256), 256>>>();
    k_scan<<<1, 1024>>>();
    k_scatter<<<ceil_div(NEDGES, 256), 256>>>(ei);

    // pre-round operands (tf32 RNA) once per launch
    k_round<<<ceil_div(NNODES * 512, 256), 256>>>(x,  xr,  NNODES * 512);
    k_round<<<ceil_div(3 * 512 * 250, 256), 256>>>(w1, W1r, 3 * 512 * 250);
    k_round<<<ceil_div(3 * 250 * 500, 256), 256>>>(w2, W2r, 3 * 250 * 500);
    k_round<<<ceil_div(3 * 500 * 1000, 256), 256>>>(w3, W3r, 3 * 500 * 1000);

    // 3 ChebConv layers
    run_layer(x,  xr, 512, 250,  W1r, b1, h1,  h1r, T1, T1r, T2r);
    run_layer(h1, h1r, 250, 500, W2r, b2, h2,  h2r, T1, T1r, T2r);
    run_layer(h2, h2r, 500, 1000, W3r, b3, out, nullptr, T1, T1r, T2r);
}

// round 11
// speedup vs baseline: 1.2233x; 1.2233x over previous
#include <cuda_runtime.h>
#include <cuda_bf16.h>
#include <cstdint>

#define NNODES 50000
#define NEDGES 1600000
#define MAXF   512

// ---------------- device scratch (static, no allocation) ----------------
__device__ int   g_flag;
__device__ int   g_deg[NNODES];
__device__ float g_dinv[NNODES];
__device__ float g_diag[NNODES];
__device__ int   g_rowptr[NNODES + 1];
__device__ int   g_cursor[NNODES];
__device__ int   g_ecol[NEDGES];
__device__ float g_ew[NEDGES];
__device__ float g_T1 [(size_t)NNODES * MAXF];
__device__ float g_T1r[(size_t)NNODES * MAXF];
__device__ float g_T2r[(size_t)NNODES * MAXF];
__device__ float g_h1 [(size_t)NNODES * 250];
__device__ float g_h1r[(size_t)NNODES * 250];
__device__ float g_h2 [(size_t)NNODES * 500];
__device__ float g_h2r[(size_t)NNODES * 500];
__device__ float g_xr [(size_t)NNODES * 512];
__device__ float g_W1r[3 * 512 * 250];
__device__ float g_W2r[3 * 250 * 500];
__device__ float g_W3r[3 * 500 * 1000];
// bf16 gather copies
__device__ __nv_bfloat16 g_xb [(size_t)NNODES * 512];
__device__ __nv_bfloat16 g_T1b[(size_t)NNODES * MAXF];
__device__ __nv_bfloat16 g_h1b[(size_t)NNODES * 250];
__device__ __nv_bfloat16 g_h2b[(size_t)NNODES * 500];

__device__ __forceinline__ float to_tf32(float x) {
    float y;
    asm("cvt.rna.tf32.f32 %0, %1;" : "=f"(y) : "f"(x));
    return y;
}

// ---------------- index width detection ----------------
__global__ void k_detect(const int* e32) {
    if (blockIdx.x == 0 && threadIdx.x == 0) {
        int is64 = 1;
        for (int i = 0; i < 512; ++i)
            if (e32[2 * i + 1] != 0) { is64 = 0; break; }
        g_flag = is64;
    }
}

__device__ __forceinline__ int load_idx(const void* e, long long i) {
    if (g_flag) return (int)((const long long*)e)[i];
    return ((const int*)e)[i];
}

// ---------------- graph setup ----------------
__global__ void k_init() {
    int i = blockIdx.x * blockDim.x + threadIdx.x;
    if (i < NNODES) { g_deg[i] = 0; g_cursor[i] = 0; }
}

__global__ void k_degree(const void* e) {
    int i = blockIdx.x * blockDim.x + threadIdx.x;
    if (i < NEDGES) {
        int dst = load_idx(e, (long long)NEDGES + i);
        atomicAdd(&g_deg[dst], 1);
    }
}

__global__ void k_node() {
    int i = blockIdx.x * blockDim.x + threadIdx.x;
    if (i < NNODES) {
        int d = g_deg[i];
        g_dinv[i] = d > 0 ? rsqrtf((float)d) : 0.0f;
        g_diag[i] = d > 0 ? 0.0f : -1.0f;
    }
}

__global__ void k_scan() {
    __shared__ int warp_sums[32];
    int tid  = threadIdx.x;
    int lane = tid & 31;
    int wid  = tid >> 5;
    int carry = 0;
    for (int base = 0; base < NNODES; base += 1024) {
        int i = base + tid;
        int v = (i < NNODES) ? g_deg[i] : 0;
        int x = v;
        #pragma unroll
        for (int o = 1; o < 32; o <<= 1) {
            int y = __shfl_up_sync(0xffffffffu, x, o);
            if (lane >= o) x += y;
        }
        if (lane == 31) warp_sums[wid] = x;
        __syncthreads();
        if (tid < 32) {
            int s = warp_sums[tid];
            #pragma unroll
            for (int o = 1; o < 32; o <<= 1) {
                int y = __shfl_up_sync(0xffffffffu, s, o);
                if (tid >= o) s += y;
            }
            warp_sums[tid] = s;
        }
        __syncthreads();
        int incl = x + (wid > 0 ? warp_sums[wid - 1] : 0);
        if (i < NNODES) g_rowptr[i] = carry + incl - v;
        int total = warp_sums[31];
        __syncthreads();
        carry += total;
    }
    if (tid == 0) g_rowptr[NNODES] = carry;
}

__global__ void k_scatter(const void* e) {
    int i = blockIdx.x * blockDim.x + threadIdx.x;
    if (i < NEDGES) {
        int src = load_idx(e, i);
        int dst = load_idx(e, (long long)NEDGES + i);
        float w = -g_dinv[dst] * g_dinv[src];
        int pos = g_rowptr[dst] + atomicAdd(&g_cursor[dst], 1);
        g_ecol[pos] = src;
        g_ew[pos]   = w;
    }
}

// ---------------- rounding helpers ----------------
__global__ void k_round(const float* __restrict__ in, float* __restrict__ dst, int n) {
    int i = blockIdx.x * blockDim.x + threadIdx.x;
    if (i < n) dst[i] = to_tf32(in[i]);
}

__global__ void k_round_dual(const float* __restrict__ in, float* __restrict__ r,
                             __nv_bfloat16* __restrict__ b, int n) {
    int i = blockIdx.x * blockDim.x + threadIdx.x;
    if (i < n) {
        float v = in[i];
        r[i] = to_tf32(v);
        b[i] = __float2bfloat16(v);
    }
}

// ---------------- bf16-gather SpMM ----------------
// acc = sum_e w_e * bf16(h[src]) ; + diag*h_fp32[node] ; mode1: 2*acc - t0
// 4 features/thread (uint2 = 4 bf16): F = 512 (128 thr), 500 (125 thr)
__global__ void k_spmm_b4(const uint2* __restrict__ hb, const float4* __restrict__ hs,
                          const float4* __restrict__ t0,
                          float4* __restrict__ out, float4* __restrict__ out_r,
                          uint2* __restrict__ out_b, int F4, int mode) {
    int node = blockIdx.x;
    int f = threadIdx.x;
    if (f >= F4) return;
    int s = g_rowptr[node];
    int e = g_rowptr[node + 1];
    float4 acc = make_float4(0.f, 0.f, 0.f, 0.f);
    for (int j = s; j < e; ++j) {
        int   src = __ldg(&g_ecol[j]);
        float w   = __ldg(&g_ew[j]);
        uint2 v = __ldg(&hb[(size_t)src * F4 + f]);
        __nv_bfloat162 p0 = *reinterpret_cast<const __nv_bfloat162*>(&v.x);
        __nv_bfloat162 p1 = *reinterpret_cast<const __nv_bfloat162*>(&v.y);
        float2 f0 = __bfloat1622float2(p0);
        float2 f1 = __bfloat1622float2(p1);
        acc.x = fmaf(w, f0.x, acc.x);
        acc.y = fmaf(w, f0.y, acc.y);
        acc.z = fmaf(w, f1.x, acc.z);
        acc.w = fmaf(w, f1.y, acc.w);
    }
    float dw = g_diag[node];
    float4 hv = __ldg(&hs[(size_t)node * F4 + f]);
    acc.x = fmaf(dw, hv.x, acc.x);
    acc.y = fmaf(dw, hv.y, acc.y);
    acc.z = fmaf(dw, hv.z, acc.z);
    acc.w = fmaf(dw, hv.w, acc.w);
    if (mode) {
        float4 t = __ldg(&t0[(size_t)node * F4 + f]);
        acc.x = 2.f * acc.x - t.x;
        acc.y = 2.f * acc.y - t.y;
        acc.z = 2.f * acc.z - t.z;
        acc.w = 2.f * acc.w - t.w;
    }
    size_t idx = (size_t)node * F4 + f;
    if (out) out[idx] = acc;
    if (out_r) out_r[idx] =
        make_float4(to_tf32(acc.x), to_tf32(acc.y), to_tf32(acc.z), to_tf32(acc.w));
    if (out_b) {
        __nv_bfloat162 b0 = __float22bfloat162_rn(make_float2(acc.x, acc.y));
        __nv_bfloat162 b1 = __float22bfloat162_rn(make_float2(acc.z, acc.w));
        uint2 u;
        u.x = *reinterpret_cast<uint32_t*>(&b0);
        u.y = *reinterpret_cast<uint32_t*>(&b1);
        out_b[idx] = u;
    }
}

// 2 features/thread (uint32 = 2 bf16): F = 250 (125 thr)
__global__ void k_spmm_b2(const uint32_t* __restrict__ hb, const float2* __restrict__ hs,
                          const float2* __restrict__ t0,
                          float2* __restrict__ out, float2* __restrict__ out_r,
                          uint32_t* __restrict__ out_b, int F2, int mode) {
    int node = blockIdx.x;
    int f = threadIdx.x;
    if (f >= F2) return;
    int s = g_rowptr[node];
    int e = g_rowptr[node + 1];
    float2 acc = make_float2(0.f, 0.f);
    for (int j = s; j < e; ++j) {
        int   src = __ldg(&g_ecol[j]);
        float w   = __ldg(&g_ew[j]);
        uint32_t v = __ldg(&hb[(size_t)src * F2 + f]);
        float2 fv = __bfloat1622float2(*reinterpret_cast<const __nv_bfloat162*>(&v));
        acc.x = fmaf(w, fv.x, acc.x);
        acc.y = fmaf(w, fv.y, acc.y);
    }
    float dw = g_diag[node];
    float2 hv = __ldg(&hs[(size_t)node * F2 + f]);
    acc.x = fmaf(dw, hv.x, acc.x);
    acc.y = fmaf(dw, hv.y, acc.y);
    if (mode) {
        float2 t = __ldg(&t0[(size_t)node * F2 + f]);
        acc.x = 2.f * acc.x - t.x;
        acc.y = 2.f * acc.y - t.y;
    }
    size_t idx = (size_t)node * F2 + f;
    if (out) out[idx] = acc;
    if (out_r) out_r[idx] = make_float2(to_tf32(acc.x), to_tf32(acc.y));
    if (out_b) {
        __nv_bfloat162 b = __float22bfloat162_rn(acc);
        out_b[idx] = *reinterpret_cast<uint32_t*>(&b);
    }
}

// ---------------- TF32 tensor-core fused GEMM (R6 config), cp.async 3-stage ----
__device__ __forceinline__ void mma_tf32(float* c, const uint32_t* a, const uint32_t* b) {
    asm volatile(
        "mma.sync.aligned.m16n8k8.row.col.f32.tf32.tf32.f32 "
        "{%0,%1,%2,%3}, {%4,%5,%6,%7}, {%8,%9}, {%0,%1,%2,%3};"
        : "+f"(c[0]), "+f"(c[1]), "+f"(c[2]), "+f"(c[3])
        : "r"(a[0]), "r"(a[1]), "r"(a[2]), "r"(a[3]), "r"(b[0]), "r"(b[1]));
}

__device__ __forceinline__ void cp_async8(uint32_t dst, const void* src, int sz) {
    asm volatile("cp.async.ca.shared.global [%0], [%1], 8, %2;"
                 :: "r"(dst), "l"(src), "r"(sz));
}
__device__ __forceinline__ void cp_commit() { asm volatile("cp.async.commit_group;"); }
template<int N> __device__ __forceinline__ void cp_wait() {
    asm volatile("cp.async.wait_group %0;" :: "n"(N));
}

#define GBM 128
#define GBN 128
#define GBK 16
#define GST 3
#define ASTRIDE 20
#define BSTRIDE 136
#define GSMEM ((GST*GBM*ASTRIDE + GST*GBK*BSTRIDE) * 4)

__global__ __launch_bounds__(256, 2) void k_gemm3_tc(
    const float* __restrict__ A0, const float* __restrict__ A1,
    const float* __restrict__ A2, const float* __restrict__ W,
    const float* __restrict__ bias, float* __restrict__ out,
    float* __restrict__ out_r, __nv_bfloat16* __restrict__ out_b,
    int M, int K, int Nout)
{
    extern __shared__ float smem[];
    float* As = smem;
    float* Bs = smem + GST * GBM * ASTRIDE;
    uint32_t sA = (uint32_t)__cvta_generic_to_shared(As);
    uint32_t sB = (uint32_t)__cvta_generic_to_shared(Bs);

    int tid  = threadIdx.x;
    int wid  = tid >> 5;
    int lane = tid & 31;
    int g    = lane >> 2;
    int tig  = lane & 3;
    int wm   = wid & 1;
    int wn   = wid >> 1;
    int bm   = blockIdx.y * GBM;
    int bn   = blockIdx.x * GBN;

    int kt = (K + GBK - 1) / GBK;
    int nt = 3 * kt;

    float acc[4][4][4];
    #pragma unroll
    for (int mi = 0; mi < 4; ++mi)
        #pragma unroll
        for (int ni = 0; ni < 4; ++ni)
            #pragma unroll
            for (int r = 0; r < 4; ++r) acc[mi][ni][r] = 0.0f;

    auto issue_tile = [&](int t) {
        int pn = t / kt;
        int k0 = (t - pn * kt) * GBK;
        int s  = t % GST;
        const float* A = (pn == 0) ? A0 : ((pn == 1) ? A1 : A2);
        #pragma unroll
        for (int q = 0; q < 4; ++q) {
            int p  = q * 256 + tid;
            int m  = p >> 3;
            int kk = (p & 7) * 2;
            int gm = bm + m, gk = k0 + kk;
            int sz = (gm < M && gk < K) ? 8 : 0;
            const float* src = sz ? (A + (size_t)gm * K + gk) : A;
            uint32_t dst = sA + (uint32_t)(((s * GBM + m) * ASTRIDE + kk) * 4);
            cp_async8(dst, src, sz);
        }
        const float* B = W + (size_t)pn * K * Nout;
        #pragma unroll
        for (int q = 0; q < 4; ++q) {
            int p  = q * 256 + tid;
            int r  = p >> 6;
            int n0 = (p & 63) * 2;
            int gk = k0 + r, gn = bn + n0;
            int sz = (gk < K && gn < Nout) ? 8 : 0;
            const float* src = sz ? (B + (size_t)gk * Nout + gn) : B;
            uint32_t dst = sB + (uint32_t)(((s * GBK + r) * BSTRIDE + n0) * 4);
            cp_async8(dst, src, sz);
        }
    };

    #pragma unroll
    for (int t = 0; t < GST - 1; ++t) {
        issue_tile(t);
        cp_commit();
    }

    for (int t = 0; t < nt; ++t) {
        cp_wait<GST - 2>();
        __syncthreads();

        int tn = t + GST - 1;
        if (tn < nt) issue_tile(tn);
        cp_commit();

        int s = t % GST;
        const float* Ab = As + s * GBM * ASTRIDE;
        const float* Bb = Bs + s * GBK * BSTRIDE;
        #pragma unroll
        for (int ks = 0; ks < GBK; ks += 8) {
            uint32_t af[4][4];
            uint32_t bf[4][2];
            #pragma unroll
            for (int mi = 0; mi < 4; ++mi) {
                int mb = wm * 64 + mi * 16;
                af[mi][0] = __float_as_uint(Ab[(mb + g    ) * ASTRIDE + ks + tig    ]);
                af[mi][1] = __float_as_uint(Ab[(mb + g + 8) * ASTRIDE + ks + tig    ]);
                af[mi][2] = __float_as_uint(Ab[(mb + g    ) * ASTRIDE + ks + tig + 4]);
                af[mi][3] = __float_as_uint(Ab[(mb + g + 8) * ASTRIDE + ks + tig + 4]);
            }
            #pragma unroll
            for (int ni = 0; ni < 4; ++ni) {
                int nb = wn * 32 + ni * 8;
                bf[ni][0] = __float_as_uint(Bb[(ks + tig    ) * BSTRIDE + nb + g]);
                bf[ni][1] = __float_as_uint(Bb[(ks + tig + 4) * BSTRIDE + nb + g]);
            }
            #pragma unroll
            for (int mi = 0; mi < 4; ++mi)
                #pragma unroll
                for (int ni = 0; ni < 4; ++ni)
                    mma_tf32(acc[mi][ni], af[mi], bf[ni]);
        }
        __syncthreads();
    }

    // ---- epilogue: bias + relu; fp32 + tf32 + bf16 outputs ----
    #pragma unroll
    for (int mi = 0; mi < 4; ++mi) {
        int r0 = bm + wm * 64 + mi * 16 + g;
        int r1 = r0 + 8;
        #pragma unroll
        for (int ni = 0; ni < 4; ++ni) {
            int c0 = bn + wn * 32 + ni * 8 + 2 * tig;
            if (c0 >= Nout) continue;            // Nout even, c0 even -> pair ok
            float bv0 = bias[c0];
            float bv1 = bias[c0 + 1];
            if (r0 < M) {
                float v0 = acc[mi][ni][0] + bv0; v0 = v0 > 0.f ? v0 : 0.f;
                float v1 = acc[mi][ni][1] + bv1; v1 = v1 > 0.f ? v1 : 0.f;
                size_t o = (size_t)r0 * Nout + c0;
                out[o] = v0; out[o + 1] = v1;
                if (out_r) { out_r[o] = to_tf32(v0); out_r[o + 1] = to_tf32(v1); }
                if (out_b) {
                    __nv_bfloat162 b = __float22bfloat162_rn(make_float2(v0, v1));
                    *reinterpret_cast<uint32_t*>(out_b + o) = *reinterpret_cast<uint32_t*>(&b);
                }
            }
            if (r1 < M) {
                float v0 = acc[mi][ni][2] + bv0; v0 = v0 > 0.f ? v0 : 0.f;
                float v1 = acc[mi][ni][3] + bv1; v1 = v1 > 0.f ? v1 : 0.f;
                size_t o = (size_t)r1 * Nout + c0;
                out[o] = v0; out[o + 1] = v1;
                if (out_r) { out_r[o] = to_tf32(v0); out_r[o + 1] = to_tf32(v1); }
                if (out_b) {
                    __nv_bfloat162 b = __float22bfloat162_rn(make_float2(v0, v1));
                    *reinterpret_cast<uint32_t*>(out_b + o) = *reinterpret_cast<uint32_t*>(&b);
                }
            }
        }
    }
}

// ---------------- host side ----------------
static inline int ceil_div(int a, int b) { return (a + b - 1) / b; }

extern "C" void kernel_launch(void* const* d_in, const int* in_sizes, int n_in,
                              void* d_out, int out_size) {
    const float* x  = (const float*)d_in[0];
    const void*  ei = d_in[1];
    const float* w1 = (const float*)d_in[2];
    const float* b1 = (const float*)d_in[3];
    const float* w2 = (const float*)d_in[4];
    const float* b2 = (const float*)d_in[5];
    const float* w3 = (const float*)d_in[6];
    const float* b3 = (const float*)d_in[7];
    float* out = (float*)d_out;

    static bool attr_set = false;
    if (!attr_set) {
        cudaFuncSetAttribute(k_gemm3_tc, cudaFuncAttributeMaxDynamicSharedMemorySize, GSMEM);
        attr_set = true;
    }

    float *T1, *T1r, *T2r, *h1, *h1r, *h2, *h2r, *xr, *W1r, *W2r, *W3r;
    __nv_bfloat16 *xb, *T1b, *h1b, *h2b;
    cudaGetSymbolAddress((void**)&T1,  g_T1);
    cudaGetSymbolAddress((void**)&T1r, g_T1r);
    cudaGetSymbolAddress((void**)&T2r, g_T2r);
    cudaGetSymbolAddress((void**)&h1,  g_h1);
    cudaGetSymbolAddress((void**)&h1r, g_h1r);
    cudaGetSymbolAddress((void**)&h2,  g_h2);
    cudaGetSymbolAddress((void**)&h2r, g_h2r);
    cudaGetSymbolAddress((void**)&xr,  g_xr);
    cudaGetSymbolAddress((void**)&W1r, g_W1r);
    cudaGetSymbolAddress((void**)&W2r, g_W2r);
    cudaGetSymbolAddress((void**)&W3r, g_W3r);
    cudaGetSymbolAddress((void**)&xb,  g_xb);
    cudaGetSymbolAddress((void**)&T1b, g_T1b);
    cudaGetSymbolAddress((void**)&h1b, g_h1b);
    cudaGetSymbolAddress((void**)&h2b, g_h2b);

    // graph setup
    k_detect<<<1, 1>>>((const int*)ei);
    k_init<<<ceil_div(NNODES, 256), 256>>>();
    k_degree<<<ceil_div(NEDGES, 256), 256>>>(ei);
    k_node<<<ceil_div(NNODES, 256), 256>>>();
    k_scan<<<1, 1024>>>();
    k_scatter<<<ceil_div(NEDGES, 256), 256>>>(ei);

    // operand prep
    k_round_dual<<<ceil_div(NNODES * 512, 256), 256>>>(x, xr, xb, NNODES * 512);
    k_round<<<ceil_div(3 * 512 * 250, 256), 256>>>(w1, W1r, 3 * 512 * 250);
    k_round<<<ceil_div(3 * 250 * 500, 256), 256>>>(w2, W2r, 3 * 250 * 500);
    k_round<<<ceil_div(3 * 500 * 1000, 256), 256>>>(w3, W3r, 3 * 500 * 1000);

    // ---- layer 1: Fin=512, Fout=250 ----
    k_spmm_b4<<<NNODES, 128>>>((const uint2*)xb, (const float4*)x, nullptr,
                               (float4*)T1, (float4*)T1r, (uint2*)T1b, 128, 0);
    k_spmm_b4<<<NNODES, 128>>>((const uint2*)T1b, (const float4*)T1, (const float4*)x,
                               nullptr, (float4*)T2r, nullptr, 128, 1);
    {
        dim3 ggrid(ceil_div(250, GBN), ceil_div(NNODES, GBM));
        k_gemm3_tc<<<ggrid, 256, GSMEM>>>(xr, T1r, T2r, W1r, b1, h1, h1r, h1b,
                                          NNODES, 512, 250);
    }

    // ---- layer 2: Fin=250, Fout=500 ----
    k_spmm_b2<<<NNODES, 125>>>((const uint32_t*)h1b, (const float2*)h1, nullptr,
                               (float2*)T1, (float2*)T1r, (uint32_t*)T1b, 125, 0);
    k_spmm_b2<<<NNODES, 125>>>((const uint32_t*)T1b, (const float2*)T1, (const float2*)h1,
                               nullptr, (float2*)T2r, nullptr, 125, 1);
    {
        dim3 ggrid(ceil_div(500, GBN), ceil_div(NNODES, GBM));
        k_gemm3_tc<<<ggrid, 256, GSMEM>>>(h1r, T1r, T2r, W2r, b2, h2, h2r, h2b,
                                          NNODES, 250, 500);
    }

    // ---- layer 3: Fin=500, Fout=1000 ----
    k_spmm_b4<<<NNODES, 125>>>((const uint2*)h2b, (const float4*)h2, nullptr,
                               (float4*)T1, (float4*)T1r, (uint2*)T1b, 125, 0);
    k_spmm_b4<<<NNODES, 125>>>((const uint2*)T1b, (const float4*)T1, (const float4*)h2,
                               nullptr, (float4*)T2r, nullptr, 125, 1);
    {
        dim3 ggrid(ceil_div(1000, GBN), ceil_div(NNODES, GBM));
        k_gemm3_tc<<<ggrid, 256, GSMEM>>>(h2r, T1r, T2r, W3r, b3, out, nullptr, nullptr,
                                          NNODES, 500, 1000);
    }
}